// round 2
// baseline (speedup 1.0000x reference)
#include <cuda_runtime.h>

// LSTMModel: 2-layer LSTM (B=2048, T=512, I=1, H=50) + FC(50->1).
// Persistent batch-partitioned CTAs: 128 CTAs x 16 batch lanes, 800 threads
// (thread = (b, k)). All weights + x-tile in SMEM. Reduction dim vectorized
// with fma.rn.f32x2 (packed f32 pairs loaded directly via LDS.128).
// h double-buffered -> 2 barriers/step.

#define HID   50
#define BT    16
#define WS    52          // padded row stride (floats), 13 x 16B
#define HS    52          // h row stride (floats), 16B-aligned rows
#define NTH   800
#define SEQL  512
#define NBATCH 2048
#define NROW  200
#define HBUF  (BT * HS)
#define GS2   650         // gate-block stride in ulonglong2 units (50*52/4)

__device__ __forceinline__ float ftanh(float v) {
    float y;
    asm("tanh.approx.f32 %0, %1;" : "=f"(y) : "f"(v));
    return y;
}
__device__ __forceinline__ float fsigm(float v) {
    return fmaf(0.5f, ftanh(0.5f * v), 0.5f);
}
__device__ __forceinline__ void fma2(unsigned long long& d,
                                     unsigned long long a, unsigned long long b) {
    asm("fma.rn.f32x2 %0, %1, %2, %0;" : "+l"(d) : "l"(a), "l"(b));
}
__device__ __forceinline__ float hsum2(unsigned long long d) {
    float lo, hi;
    asm("mov.b64 {%0, %1}, %2;" : "=f"(lo), "=f"(hi) : "l"(d));
    return lo + hi;
}

__global__ __launch_bounds__(NTH, 1)
void lstm2_kernel(const float* __restrict__ x,
                  const float* __restrict__ W_ih0, const float* __restrict__ W_hh0,
                  const float* __restrict__ b_ih0, const float* __restrict__ b_hh0,
                  const float* __restrict__ W_ih1, const float* __restrict__ W_hh1,
                  const float* __restrict__ b_ih1, const float* __restrict__ b_hh1,
                  const float* __restrict__ fc_W, const float* __restrict__ fc_b,
                  float* __restrict__ out)
{
    extern __shared__ float sm[];
    float* sW0  = sm;                    // W_hh0  [200][WS]
    float* sWi1 = sW0  + NROW * WS;      // W_ih1  [200][WS]
    float* sWh1 = sWi1 + NROW * WS;      // W_hh1  [200][WS]
    float* sX   = sWh1 + NROW * WS;      // x tile [BT][SEQL]
    float* h1s  = sX   + BT * SEQL;      // 2 bufs [BT][HS]
    float* h2s  = h1s  + 2 * HBUF;       // 2 bufs [BT][HS]

    const int tid = threadIdx.x;
    const int b   = tid & 15;
    const int k   = tid >> 4;
    const int bg  = blockIdx.x * BT;

    // ---- prologue: stage weights (zero-padded cols 50..51) + x tile ----
    for (int i = tid; i < NROW * WS; i += NTH) {
        int r = i / WS, c = i - r * WS;
        bool in = (c < HID);
        sW0 [i] = in ? W_hh0[r * HID + c] : 0.0f;
        sWi1[i] = in ? W_ih1[r * HID + c] : 0.0f;
        sWh1[i] = in ? W_hh1[r * HID + c] : 0.0f;
    }
    for (int i = tid; i < BT * SEQL; i += NTH) {
        int bl = i >> 9;
        int t  = i & (SEQL - 1);
        sX[i] = x[(size_t)(bg + bl) * SEQL + t];
    }
    for (int i = tid; i < 4 * HBUF; i += NTH) h1s[i] = 0.0f;  // h1s+h2s contiguous

    float wi0[4], bs0[4], bs1[4];
    #pragma unroll
    for (int g = 0; g < 4; g++) {
        int r = g * HID + k;
        wi0[g] = W_ih0[r];
        bs0[g] = b_ih0[r] + b_hh0[r];
        bs1[g] = b_ih1[r] + b_hh1[r];
    }
    float c1 = 0.0f, c2 = 0.0f;
    __syncthreads();

    const ulonglong2* w0k  = (const ulonglong2*)(sW0  + k * WS);
    const ulonglong2* wi1k = (const ulonglong2*)(sWi1 + k * WS);
    const ulonglong2* wh1k = (const ulonglong2*)(sWh1 + k * WS);
    const float* sxb = sX + b * SEQL;

    for (int t = 0; t < SEQL; t++) {
        const int p = t & 1, q = p ^ 1;
        const ulonglong2* h1r = (const ulonglong2*)(h1s + p * HBUF + b * HS);
        const ulonglong2* h2r = (const ulonglong2*)(h2s + p * HBUF + b * HS);

        unsigned long long a10 = 0, a11 = 0, a12 = 0, a13 = 0;
        unsigned long long a20 = 0, a21 = 0, a22 = 0, a23 = 0;

        // Phase A: W_hh0 . h1[t-1]  and  W_hh1 . h2[t-1]
        #pragma unroll
        for (int j = 0; j < 13; j++) {
            ulonglong2 hv1 = h1r[j];
            ulonglong2 hv2 = h2r[j];
            ulonglong2 w;
            w = w0k [j];           fma2(a10, w.x, hv1.x); fma2(a10, w.y, hv1.y);
            w = w0k [j + GS2];     fma2(a11, w.x, hv1.x); fma2(a11, w.y, hv1.y);
            w = w0k [j + 2 * GS2]; fma2(a12, w.x, hv1.x); fma2(a12, w.y, hv1.y);
            w = w0k [j + 3 * GS2]; fma2(a13, w.x, hv1.x); fma2(a13, w.y, hv1.y);
            w = wh1k[j];           fma2(a20, w.x, hv2.x); fma2(a20, w.y, hv2.y);
            w = wh1k[j + GS2];     fma2(a21, w.x, hv2.x); fma2(a21, w.y, hv2.y);
            w = wh1k[j + 2 * GS2]; fma2(a22, w.x, hv2.x); fma2(a22, w.y, hv2.y);
            w = wh1k[j + 3 * GS2]; fma2(a23, w.x, hv2.x); fma2(a23, w.y, hv2.y);
        }

        float xt = sxb[t];
        float g0 = hsum2(a10) + fmaf(xt, wi0[0], bs0[0]);
        float g1 = hsum2(a11) + fmaf(xt, wi0[1], bs0[1]);
        float g2 = hsum2(a12) + fmaf(xt, wi0[2], bs0[2]);
        float g3 = hsum2(a13) + fmaf(xt, wi0[3], bs0[3]);

        float i1 = fsigm(g0), f1 = fsigm(g1), gg1 = ftanh(g2), o1 = fsigm(g3);
        c1 = fmaf(f1, c1, i1 * gg1);
        float h1n = o1 * ftanh(c1);

        float* h1wp = h1s + q * HBUF;
        h1wp[b * HS + k] = h1n;
        __syncthreads();                 // h1[t] visible

        // Phase C: W_ih1 . h1[t]
        const ulonglong2* h1w = (const ulonglong2*)(h1wp + b * HS);
        #pragma unroll
        for (int j = 0; j < 13; j++) {
            ulonglong2 hv = h1w[j];
            ulonglong2 w;
            w = wi1k[j];           fma2(a20, w.x, hv.x); fma2(a20, w.y, hv.y);
            w = wi1k[j + GS2];     fma2(a21, w.x, hv.x); fma2(a21, w.y, hv.y);
            w = wi1k[j + 2 * GS2]; fma2(a22, w.x, hv.x); fma2(a22, w.y, hv.y);
            w = wi1k[j + 3 * GS2]; fma2(a23, w.x, hv.x); fma2(a23, w.y, hv.y);
        }

        float g4 = hsum2(a20) + bs1[0];
        float g5 = hsum2(a21) + bs1[1];
        float g6 = hsum2(a22) + bs1[2];
        float g7 = hsum2(a23) + bs1[3];

        float i2 = fsigm(g4), f2 = fsigm(g5), gg2 = ftanh(g6), o2 = fsigm(g7);
        c2 = fmaf(f2, c2, i2 * gg2);
        float h2n = o2 * ftanh(c2);
        (h2s + q * HBUF)[b * HS + k] = h2n;
        __syncthreads();                 // h2[t] visible; also protects buf reuse
    }

    // ---- epilogue: out[b] = h2_last . fc_W + fc_b ----
    if (k == 0) {
        const float* h2f = h2s + (SEQL & 1) * HBUF;
        float acc = fc_b[0];
        #pragma unroll
        for (int kk = 0; kk < HID; kk++)
            acc = fmaf(h2f[b * HS + kk], fc_W[kk], acc);
        out[bg + b] = acc;
    }
}

extern "C" void kernel_launch(void* const* d_in, const int* in_sizes, int n_in,
                              void* d_out, int out_size)
{
    const float* x     = (const float*)d_in[0];
    const float* W_ih0 = (const float*)d_in[1];
    const float* W_hh0 = (const float*)d_in[2];
    const float* b_ih0 = (const float*)d_in[3];
    const float* b_hh0 = (const float*)d_in[4];
    const float* W_ih1 = (const float*)d_in[5];
    const float* W_hh1 = (const float*)d_in[6];
    const float* b_ih1 = (const float*)d_in[7];
    const float* b_hh1 = (const float*)d_in[8];
    const float* fc_W  = (const float*)d_in[9];
    const float* fc_b  = (const float*)d_in[10];
    float* out = (float*)d_out;

    const int smem_bytes = (3 * NROW * WS + BT * SEQL + 4 * HBUF) * (int)sizeof(float);
    cudaFuncSetAttribute(lstm2_kernel, cudaFuncAttributeMaxDynamicSharedMemorySize, smem_bytes);
    lstm2_kernel<<<NBATCH / BT, NTH, smem_bytes>>>(
        x, W_ih0, W_hh0, b_ih0, b_hh0,
        W_ih1, W_hh1, b_ih1, b_hh1, fc_W, fc_b, out);
}

// round 3
// speedup vs baseline: 1.2872x; 1.2872x over previous
#include <cuda_runtime.h>

// LSTMModel: 2-layer LSTM (B=2048, T=512, I=1, H=50) + FC(50->1).
// Persistent batch-partitioned CTAs: 128 CTAs x 16 batch. 400 threads:
// thread = (b in [0,8), k in [0,50)), each thread handles batches b and b+8
// (weight wavefronts amortized 2x; h-loads single-wavefront).
// Reduction vectorized with fma.rn.f32x2 on 128-bit SMEM loads.

#define HID   50
#define BT    16
#define WS    52          // padded row stride (floats), 13 x 16B
#define HS    52
#define NTH   400
#define SEQL  512
#define NBATCH 2048
#define NROW  200
#define HBUF  (BT * HS)
#define GS2   650         // gate-block stride in ulonglong2 units (50*52/4)

__device__ __forceinline__ float ftanh(float v) {
    float y;
    asm("tanh.approx.f32 %0, %1;" : "=f"(y) : "f"(v));
    return y;
}
__device__ __forceinline__ float fsigm(float v) {
    return fmaf(0.5f, ftanh(0.5f * v), 0.5f);
}
__device__ __forceinline__ void fma2(unsigned long long& d,
                                     unsigned long long a, unsigned long long b) {
    asm("fma.rn.f32x2 %0, %1, %2, %0;" : "+l"(d) : "l"(a), "l"(b));
}
__device__ __forceinline__ float hsum2(unsigned long long d) {
    float lo, hi;
    asm("mov.b64 {%0, %1}, %2;" : "=f"(lo), "=f"(hi) : "l"(d));
    return lo + hi;
}

__global__ __launch_bounds__(NTH, 1)
void lstm2_kernel(const float* __restrict__ x,
                  const float* __restrict__ W_ih0, const float* __restrict__ W_hh0,
                  const float* __restrict__ b_ih0, const float* __restrict__ b_hh0,
                  const float* __restrict__ W_ih1, const float* __restrict__ W_hh1,
                  const float* __restrict__ b_ih1, const float* __restrict__ b_hh1,
                  const float* __restrict__ fc_W, const float* __restrict__ fc_b,
                  float* __restrict__ out)
{
    extern __shared__ float sm[];
    float* sW0  = sm;                    // W_hh0  [200][WS]
    float* sWi1 = sW0  + NROW * WS;      // W_ih1  [200][WS]
    float* sWh1 = sWi1 + NROW * WS;      // W_hh1  [200][WS]
    float* sX   = sWh1 + NROW * WS;      // x tile [BT][SEQL]
    float* h1s  = sX   + BT * SEQL;      // 2 bufs [BT][HS]
    float* h2s  = h1s  + 2 * HBUF;       // 2 bufs [BT][HS]

    const int tid = threadIdx.x;
    const int b   = tid & 7;             // first batch lane; second is b+8
    const int k   = tid >> 3;            // hidden index 0..49
    const int bg  = blockIdx.x * BT;

    // ---- prologue: stage weights (zero-padded cols 50..51) + x tile ----
    for (int i = tid; i < NROW * WS; i += NTH) {
        int r = i / WS, c = i - r * WS;
        bool in = (c < HID);
        sW0 [i] = in ? W_hh0[r * HID + c] : 0.0f;
        sWi1[i] = in ? W_ih1[r * HID + c] : 0.0f;
        sWh1[i] = in ? W_hh1[r * HID + c] : 0.0f;
    }
    for (int i = tid; i < BT * SEQL; i += NTH) {
        int bl = i >> 9;
        int t  = i & (SEQL - 1);
        sX[i] = x[(size_t)(bg + bl) * SEQL + t];
    }
    for (int i = tid; i < 4 * HBUF; i += NTH) h1s[i] = 0.0f;  // h1s+h2s contiguous

    float wi0[4], bs0[4], bs1[4];
    #pragma unroll
    for (int g = 0; g < 4; g++) {
        int r = g * HID + k;
        wi0[g] = W_ih0[r];
        bs0[g] = b_ih0[r] + b_hh0[r];
        bs1[g] = b_ih1[r] + b_hh1[r];
    }
    float c1a = 0.0f, c2a = 0.0f;   // batch b
    float c1b = 0.0f, c2b = 0.0f;   // batch b+8
    __syncthreads();

    const ulonglong2* w0k  = (const ulonglong2*)(sW0  + k * WS);
    const ulonglong2* wi1k = (const ulonglong2*)(sWi1 + k * WS);
    const ulonglong2* wh1k = (const ulonglong2*)(sWh1 + k * WS);
    const float* sxa = sX + b * SEQL;
    const float* sxb = sX + (b + 8) * SEQL;

    for (int t = 0; t < SEQL; t++) {
        const int p = t & 1, q = p ^ 1;
        const ulonglong2* h1ra = (const ulonglong2*)(h1s + p * HBUF + b * HS);
        const ulonglong2* h1rb = (const ulonglong2*)(h1s + p * HBUF + (b + 8) * HS);
        const ulonglong2* h2ra = (const ulonglong2*)(h2s + p * HBUF + b * HS);
        const ulonglong2* h2rb = (const ulonglong2*)(h2s + p * HBUF + (b + 8) * HS);

        unsigned long long a10a = 0, a11a = 0, a12a = 0, a13a = 0;
        unsigned long long a10b = 0, a11b = 0, a12b = 0, a13b = 0;
        unsigned long long a20a = 0, a21a = 0, a22a = 0, a23a = 0;
        unsigned long long a20b = 0, a21b = 0, a22b = 0, a23b = 0;

        // Phase A: W_hh0 . h1[t-1] and W_hh1 . h2[t-1], 2 batches each
        #pragma unroll
        for (int j = 0; j < 13; j++) {
            ulonglong2 hA1 = h1ra[j], hB1 = h1rb[j];
            ulonglong2 hA2 = h2ra[j], hB2 = h2rb[j];
            ulonglong2 w;
            w = w0k [j];
            fma2(a10a, w.x, hA1.x); fma2(a10a, w.y, hA1.y);
            fma2(a10b, w.x, hB1.x); fma2(a10b, w.y, hB1.y);
            w = w0k [j + GS2];
            fma2(a11a, w.x, hA1.x); fma2(a11a, w.y, hA1.y);
            fma2(a11b, w.x, hB1.x); fma2(a11b, w.y, hB1.y);
            w = w0k [j + 2 * GS2];
            fma2(a12a, w.x, hA1.x); fma2(a12a, w.y, hA1.y);
            fma2(a12b, w.x, hB1.x); fma2(a12b, w.y, hB1.y);
            w = w0k [j + 3 * GS2];
            fma2(a13a, w.x, hA1.x); fma2(a13a, w.y, hA1.y);
            fma2(a13b, w.x, hB1.x); fma2(a13b, w.y, hB1.y);
            w = wh1k[j];
            fma2(a20a, w.x, hA2.x); fma2(a20a, w.y, hA2.y);
            fma2(a20b, w.x, hB2.x); fma2(a20b, w.y, hB2.y);
            w = wh1k[j + GS2];
            fma2(a21a, w.x, hA2.x); fma2(a21a, w.y, hA2.y);
            fma2(a21b, w.x, hB2.x); fma2(a21b, w.y, hB2.y);
            w = wh1k[j + 2 * GS2];
            fma2(a22a, w.x, hA2.x); fma2(a22a, w.y, hA2.y);
            fma2(a22b, w.x, hB2.x); fma2(a22b, w.y, hB2.y);
            w = wh1k[j + 3 * GS2];
            fma2(a23a, w.x, hA2.x); fma2(a23a, w.y, hA2.y);
            fma2(a23b, w.x, hB2.x); fma2(a23b, w.y, hB2.y);
        }

        // layer-1 gates for both batches
        float xta = sxa[t], xtb = sxb[t];
        float g0a = hsum2(a10a) + fmaf(xta, wi0[0], bs0[0]);
        float g1a = hsum2(a11a) + fmaf(xta, wi0[1], bs0[1]);
        float g2a = hsum2(a12a) + fmaf(xta, wi0[2], bs0[2]);
        float g3a = hsum2(a13a) + fmaf(xta, wi0[3], bs0[3]);
        float g0b = hsum2(a10b) + fmaf(xtb, wi0[0], bs0[0]);
        float g1b = hsum2(a11b) + fmaf(xtb, wi0[1], bs0[1]);
        float g2b = hsum2(a12b) + fmaf(xtb, wi0[2], bs0[2]);
        float g3b = hsum2(a13b) + fmaf(xtb, wi0[3], bs0[3]);

        float i1, f1, gg1, o1;
        i1 = fsigm(g0a); f1 = fsigm(g1a); gg1 = ftanh(g2a); o1 = fsigm(g3a);
        c1a = fmaf(f1, c1a, i1 * gg1);
        float h1na = o1 * ftanh(c1a);
        i1 = fsigm(g0b); f1 = fsigm(g1b); gg1 = ftanh(g2b); o1 = fsigm(g3b);
        c1b = fmaf(f1, c1b, i1 * gg1);
        float h1nb = o1 * ftanh(c1b);

        float* h1wp = h1s + q * HBUF;
        h1wp[b * HS + k]       = h1na;
        h1wp[(b + 8) * HS + k] = h1nb;
        __syncthreads();                 // h1[t] visible

        // Phase C: W_ih1 . h1[t], 2 batches
        const ulonglong2* h1wa = (const ulonglong2*)(h1wp + b * HS);
        const ulonglong2* h1wb = (const ulonglong2*)(h1wp + (b + 8) * HS);
        #pragma unroll
        for (int j = 0; j < 13; j++) {
            ulonglong2 hA = h1wa[j], hB = h1wb[j];
            ulonglong2 w;
            w = wi1k[j];
            fma2(a20a, w.x, hA.x); fma2(a20a, w.y, hA.y);
            fma2(a20b, w.x, hB.x); fma2(a20b, w.y, hB.y);
            w = wi1k[j + GS2];
            fma2(a21a, w.x, hA.x); fma2(a21a, w.y, hA.y);
            fma2(a21b, w.x, hB.x); fma2(a21b, w.y, hB.y);
            w = wi1k[j + 2 * GS2];
            fma2(a22a, w.x, hA.x); fma2(a22a, w.y, hA.y);
            fma2(a22b, w.x, hB.x); fma2(a22b, w.y, hB.y);
            w = wi1k[j + 3 * GS2];
            fma2(a23a, w.x, hA.x); fma2(a23a, w.y, hA.y);
            fma2(a23b, w.x, hB.x); fma2(a23b, w.y, hB.y);
        }

        float g4a = hsum2(a20a) + bs1[0];
        float g5a = hsum2(a21a) + bs1[1];
        float g6a = hsum2(a22a) + bs1[2];
        float g7a = hsum2(a23a) + bs1[3];
        float g4b = hsum2(a20b) + bs1[0];
        float g5b = hsum2(a21b) + bs1[1];
        float g6b = hsum2(a22b) + bs1[2];
        float g7b = hsum2(a23b) + bs1[3];

        float i2, f2, gg2, o2;
        i2 = fsigm(g4a); f2 = fsigm(g5a); gg2 = ftanh(g6a); o2 = fsigm(g7a);
        c2a = fmaf(f2, c2a, i2 * gg2);
        float h2na = o2 * ftanh(c2a);
        i2 = fsigm(g4b); f2 = fsigm(g5b); gg2 = ftanh(g6b); o2 = fsigm(g7b);
        c2b = fmaf(f2, c2b, i2 * gg2);
        float h2nb = o2 * ftanh(c2b);

        float* h2wp = h2s + q * HBUF;
        h2wp[b * HS + k]       = h2na;
        h2wp[(b + 8) * HS + k] = h2nb;
        __syncthreads();                 // h2[t] visible before next Phase A
    }

    // ---- epilogue: out[b] = h2_last . fc_W + fc_b ----
    if (k == 0) {
        const float* h2f = h2s + (SEQL & 1) * HBUF;
        float acca = fc_b[0], accb = fc_b[0];
        #pragma unroll
        for (int kk = 0; kk < HID; kk++) {
            float w = fc_W[kk];
            acca = fmaf(h2f[b * HS + kk],       w, acca);
            accb = fmaf(h2f[(b + 8) * HS + kk], w, accb);
        }
        out[bg + b]     = acca;
        out[bg + b + 8] = accb;
    }
}

extern "C" void kernel_launch(void* const* d_in, const int* in_sizes, int n_in,
                              void* d_out, int out_size)
{
    const float* x     = (const float*)d_in[0];
    const float* W_ih0 = (const float*)d_in[1];
    const float* W_hh0 = (const float*)d_in[2];
    const float* b_ih0 = (const float*)d_in[3];
    const float* b_hh0 = (const float*)d_in[4];
    const float* W_ih1 = (const float*)d_in[5];
    const float* W_hh1 = (const float*)d_in[6];
    const float* b_ih1 = (const float*)d_in[7];
    const float* b_hh1 = (const float*)d_in[8];
    const float* fc_W  = (const float*)d_in[9];
    const float* fc_b  = (const float*)d_in[10];
    float* out = (float*)d_out;

    const int smem_bytes = (3 * NROW * WS + BT * SEQL + 4 * HBUF) * (int)sizeof(float);
    cudaFuncSetAttribute(lstm2_kernel, cudaFuncAttributeMaxDynamicSharedMemorySize, smem_bytes);
    lstm2_kernel<<<NBATCH / BT, NTH, smem_bytes>>>(
        x, W_ih0, W_hh0, b_ih0, b_hh0,
        W_ih1, W_hh1, b_ih1, b_hh1, fc_W, fc_b, out);
}

// round 4
// speedup vs baseline: 1.7576x; 1.3654x over previous
#include <cuda_runtime.h>

// 2-layer LSTM (B=2048, T=512, I=1, H=50) + FC(50->1).
// Persistent CTAs: 128 CTAs x 16 batch. 224 threads: thread = (b in [0,4),
// k in [0,56)), k>=50 are dummy lanes. Each thread handles 4 batches
// (b, b+4, b+8, b+12) -> weight LDS amortized 4x. Layer-skewed: iteration u
// computes L1(t=u) and L2(t=u-1) in one block, ONE barrier per step.
// Math: fma.rn.f32x2 on 128-bit SMEM loads.

#define HID   50
#define KP    56          // padded hidden rows (8 | KP)
#define BT    16
#define WS    52          // weight row stride (floats) = 13 x 16B
#define HS    52          // h row stride (floats)
#define SXS   513         // x row stride (floats), odd -> conflict-free
#define NTH   224
#define SEQL  512
#define NBATCH 2048
#define HBUF  (BT * HS)
#define GS2   (KP * WS / 4)   // gate-block stride in ulonglong2 = 728

__device__ __forceinline__ float ftanh(float v) {
    float y;
    asm("tanh.approx.f32 %0, %1;" : "=f"(y) : "f"(v));
    return y;
}
__device__ __forceinline__ float fsigm(float v) {
    return fmaf(0.5f, ftanh(0.5f * v), 0.5f);
}
__device__ __forceinline__ void fma2(unsigned long long& d,
                                     unsigned long long a, unsigned long long b) {
    asm("fma.rn.f32x2 %0, %1, %2, %0;" : "+l"(d) : "l"(a), "l"(b));
}
__device__ __forceinline__ float hsum2(unsigned long long d) {
    float lo, hi;
    asm("mov.b64 {%0, %1}, %2;" : "=f"(lo), "=f"(hi) : "l"(d));
    return lo + hi;
}

__global__ __launch_bounds__(NTH, 1)
void lstm2_kernel(const float* __restrict__ x,
                  const float* __restrict__ W_ih0, const float* __restrict__ W_hh0,
                  const float* __restrict__ b_ih0, const float* __restrict__ b_hh0,
                  const float* __restrict__ W_ih1, const float* __restrict__ W_hh1,
                  const float* __restrict__ b_ih1, const float* __restrict__ b_hh1,
                  const float* __restrict__ fc_W, const float* __restrict__ fc_b,
                  float* __restrict__ out)
{
    extern __shared__ float sm[];
    float* sW0  = sm;                    // W_hh0  [4*KP][WS]
    float* sWi1 = sW0  + 4 * KP * WS;    // W_ih1
    float* sWh1 = sWi1 + 4 * KP * WS;    // W_hh1
    float* sX   = sWh1 + 4 * KP * WS;    // x tile [BT][SXS]
    float* h1s  = sX   + BT * SXS;       // 2 bufs [BT][HS]
    float* h2s  = h1s  + 2 * HBUF;       // 2 bufs [BT][HS]

    const int tid = threadIdx.x;
    const int b   = tid & 3;             // batch lane; handles b, b+4, b+8, b+12
    const int k   = tid >> 2;            // 0..55 (50..55 dummy)
    const bool act = (k < HID);
    const int bg  = blockIdx.x * BT;

    // ---- prologue ----
    for (int i = tid; i < 4 * KP * WS; i += NTH) {
        int r = i / WS, c = i - r * WS;
        int g = r / KP, kr = r - g * KP;
        bool in = (kr < HID) && (c < HID);
        int src = (g * HID + kr) * HID + c;
        sW0 [i] = in ? W_hh0[src] : 0.0f;
        sWi1[i] = in ? W_ih1[src] : 0.0f;
        sWh1[i] = in ? W_hh1[src] : 0.0f;
    }
    for (int i = tid; i < BT * SEQL; i += NTH) {
        int bl = i >> 9;
        int t  = i & (SEQL - 1);
        sX[bl * SXS + t] = x[(size_t)(bg + bl) * SEQL + t];
    }
    for (int i = tid; i < 4 * HBUF; i += NTH) h1s[i] = 0.0f;  // h1s+h2s contiguous

    const int ksafe = act ? k : 0;
    float wi0[4], bs0[4], bs1[4];
    #pragma unroll
    for (int g = 0; g < 4; g++) {
        int r = g * HID + ksafe;
        wi0[g] = W_ih0[r];
        bs0[g] = b_ih0[r] + b_hh0[r];
        bs1[g] = b_ih1[r] + b_hh1[r];
    }
    float c1[4] = {0, 0, 0, 0}, c2[4] = {0, 0, 0, 0};
    __syncthreads();

    const ulonglong2* w0k  = (const ulonglong2*)(sW0  + k * WS);
    const ulonglong2* wi1k = (const ulonglong2*)(sWi1 + k * WS);
    const ulonglong2* wh1k = (const ulonglong2*)(sWh1 + k * WS);

    // ---- peel t=0 for layer 1: h1[-1]=0 so gates = bs0 + wi0*x[0] ----
    {
        float* h1w = h1s;                // buf 0 (u=0 -> u&1 = 0)
        #pragma unroll
        for (int bb = 0; bb < 4; bb++) {
            float xt = sX[(b + 4 * bb) * SXS];
            float i1 = fsigm(fmaf(xt, wi0[0], bs0[0]));
            float f1 = fsigm(fmaf(xt, wi0[1], bs0[1]));
            float g1 = ftanh(fmaf(xt, wi0[2], bs0[2]));
            float o1 = fsigm(fmaf(xt, wi0[3], bs0[3]));
            c1[bb] = i1 * g1;            // f1*0 + i1*g1
            (void)f1;
            if (act) h1w[(b + 4 * bb) * HS + k] = o1 * ftanh(c1[bb]);
        }
        __syncthreads();
    }

    // ---- main skewed loop: u = 1..511 -> L1(t=u) + L2(t=u-1) ----
    for (int u = 1; u < SEQL; u++) {
        const float* h1r = h1s + ((u + 1) & 1) * HBUF;   // h1[u-1]
        const float* h2r = h2s + (u & 1) * HBUF;         // h2[u-2]
        float* h1w = h1s + (u & 1) * HBUF;               // h1[u]
        float* h2w = h2s + ((u + 1) & 1) * HBUF;         // h2[u-1]

        unsigned long long a1[4][4], a2[4][4];
        #pragma unroll
        for (int g = 0; g < 4; g++)
            #pragma unroll
            for (int bb = 0; bb < 4; bb++) { a1[g][bb] = 0ULL; a2[g][bb] = 0ULL; }

        #pragma unroll
        for (int j = 0; j < 13; j++) {
            ulonglong2 h1v[4], h2v[4];
            #pragma unroll
            for (int bb = 0; bb < 4; bb++) {
                h1v[bb] = ((const ulonglong2*)(h1r + (b + 4 * bb) * HS))[j];
                h2v[bb] = ((const ulonglong2*)(h2r + (b + 4 * bb) * HS))[j];
            }
            #pragma unroll
            for (int g = 0; g < 4; g++) {
                ulonglong2 w;
                w = w0k[j + g * GS2];          // L1 recurrent
                #pragma unroll
                for (int bb = 0; bb < 4; bb++) {
                    fma2(a1[g][bb], w.x, h1v[bb].x);
                    fma2(a1[g][bb], w.y, h1v[bb].y);
                }
                w = wh1k[j + g * GS2];         // L2 recurrent (h2[u-2])
                #pragma unroll
                for (int bb = 0; bb < 4; bb++) {
                    fma2(a2[g][bb], w.x, h2v[bb].x);
                    fma2(a2[g][bb], w.y, h2v[bb].y);
                }
                w = wi1k[j + g * GS2];         // L2 input (h1[u-1])
                #pragma unroll
                for (int bb = 0; bb < 4; bb++) {
                    fma2(a2[g][bb], w.x, h1v[bb].x);
                    fma2(a2[g][bb], w.y, h1v[bb].y);
                }
            }
        }

        #pragma unroll
        for (int bb = 0; bb < 4; bb++) {
            // layer 1 at t=u
            float xt = sX[(b + 4 * bb) * SXS + u];
            float g0 = hsum2(a1[0][bb]) + fmaf(xt, wi0[0], bs0[0]);
            float g1 = hsum2(a1[1][bb]) + fmaf(xt, wi0[1], bs0[1]);
            float g2 = hsum2(a1[2][bb]) + fmaf(xt, wi0[2], bs0[2]);
            float g3 = hsum2(a1[3][bb]) + fmaf(xt, wi0[3], bs0[3]);
            float i1 = fsigm(g0), f1 = fsigm(g1), gg1 = ftanh(g2), o1 = fsigm(g3);
            c1[bb] = fmaf(f1, c1[bb], i1 * gg1);
            float h1n = o1 * ftanh(c1[bb]);
            // layer 2 at t=u-1
            float G0 = hsum2(a2[0][bb]) + bs1[0];
            float G1 = hsum2(a2[1][bb]) + bs1[1];
            float G2 = hsum2(a2[2][bb]) + bs1[2];
            float G3 = hsum2(a2[3][bb]) + bs1[3];
            float i2 = fsigm(G0), f2 = fsigm(G1), gg2 = ftanh(G2), o2 = fsigm(G3);
            c2[bb] = fmaf(f2, c2[bb], i2 * gg2);
            float h2n = o2 * ftanh(c2[bb]);
            if (act) {
                h1w[(b + 4 * bb) * HS + k] = h1n;
                h2w[(b + 4 * bb) * HS + k] = h2n;
            }
        }
        __syncthreads();
    }

    // ---- tail: L2 at t=511 (u=512) ----
    {
        const float* h1r = h1s + HBUF;   // h1[511] (buf 1)
        const float* h2r = h2s;          // h2[510] (buf 0)
        unsigned long long a2[4][4];
        #pragma unroll
        for (int g = 0; g < 4; g++)
            #pragma unroll
            for (int bb = 0; bb < 4; bb++) a2[g][bb] = 0ULL;

        #pragma unroll
        for (int j = 0; j < 13; j++) {
            ulonglong2 h1v[4], h2v[4];
            #pragma unroll
            for (int bb = 0; bb < 4; bb++) {
                h1v[bb] = ((const ulonglong2*)(h1r + (b + 4 * bb) * HS))[j];
                h2v[bb] = ((const ulonglong2*)(h2r + (b + 4 * bb) * HS))[j];
            }
            #pragma unroll
            for (int g = 0; g < 4; g++) {
                ulonglong2 w;
                w = wh1k[j + g * GS2];
                #pragma unroll
                for (int bb = 0; bb < 4; bb++) {
                    fma2(a2[g][bb], w.x, h2v[bb].x);
                    fma2(a2[g][bb], w.y, h2v[bb].y);
                }
                w = wi1k[j + g * GS2];
                #pragma unroll
                for (int bb = 0; bb < 4; bb++) {
                    fma2(a2[g][bb], w.x, h1v[bb].x);
                    fma2(a2[g][bb], w.y, h1v[bb].y);
                }
            }
        }

        float* h2f = h2s + HBUF;         // scratch (h2[509], dead)
        #pragma unroll
        for (int bb = 0; bb < 4; bb++) {
            float G0 = hsum2(a2[0][bb]) + bs1[0];
            float G1 = hsum2(a2[1][bb]) + bs1[1];
            float G2 = hsum2(a2[2][bb]) + bs1[2];
            float G3 = hsum2(a2[3][bb]) + bs1[3];
            float i2 = fsigm(G0), f2 = fsigm(G1), gg2 = ftanh(G2), o2 = fsigm(G3);
            c2[bb] = fmaf(f2, c2[bb], i2 * gg2);
            if (act) h2f[(b + 4 * bb) * HS + k] = o2 * ftanh(c2[bb]);
        }
        __syncthreads();

        // FC: out[b'] = h2[511] . fc_W + fc_b   (threads k==0, 4 batches each)
        if (k == 0) {
            float fb = fc_b[0];
            #pragma unroll
            for (int bb = 0; bb < 4; bb++) {
                float acc = fb;
                const float* hrow = h2f + (b + 4 * bb) * HS;
                #pragma unroll
                for (int kk = 0; kk < HID; kk++)
                    acc = fmaf(hrow[kk], fc_W[kk], acc);
                out[bg + b + 4 * bb] = acc;
            }
        }
    }
}

extern "C" void kernel_launch(void* const* d_in, const int* in_sizes, int n_in,
                              void* d_out, int out_size)
{
    const float* x     = (const float*)d_in[0];
    const float* W_ih0 = (const float*)d_in[1];
    const float* W_hh0 = (const float*)d_in[2];
    const float* b_ih0 = (const float*)d_in[3];
    const float* b_hh0 = (const float*)d_in[4];
    const float* W_ih1 = (const float*)d_in[5];
    const float* W_hh1 = (const float*)d_in[6];
    const float* b_ih1 = (const float*)d_in[7];
    const float* b_hh1 = (const float*)d_in[8];
    const float* fc_W  = (const float*)d_in[9];
    const float* fc_b  = (const float*)d_in[10];
    float* out = (float*)d_out;

    const int smem_bytes = (3 * 4 * KP * WS + BT * SXS + 4 * HBUF) * (int)sizeof(float);
    cudaFuncSetAttribute(lstm2_kernel, cudaFuncAttributeMaxDynamicSharedMemorySize, smem_bytes);
    lstm2_kernel<<<NBATCH / BT, NTH, smem_bytes>>>(
        x, W_ih0, W_hh0, b_ih0, b_hh0,
        W_ih1, W_hh1, b_ih1, b_hh1, fc_W, fc_b, out);
}